// round 3
// baseline (speedup 1.0000x reference)
#include <cuda_runtime.h>
#include <math.h>

#define B_   128
#define L_   64
#define D_   256
#define H_   512
#define AS_  512
#define AP_  256
#define G3H_ 1536
#define NEGV (-1.0e9f)

// ---------------- scratch (device globals; no allocation allowed) ----------------
__device__ float g_dense   [B_*L_*D_];     // dense_inputs [B,L,D]
__device__ float g_enc_gi  [B_*L_*G3H_];   // x@enc_Wi.T for all (b,t)
__device__ float g_decx_gi [B_*L_*G3H_];   // dense_inputs@dec_Wi[:,H:].T for all (b,l)
__device__ float g_enc_out [B_*L_*H_];     // masked encoder states
__device__ float g_enc_keys[B_*L_*AS_];
__device__ float g_ptr_keys[B_*L_*AP_];
__device__ float g_h   [B_*H_];
__device__ float g_gh  [B_*G3H_];
__device__ float g_gic [B_*G3H_];
__device__ float g_ctx [B_*H_];
__device__ float g_q   [B_*AS_];
__device__ float g_dout[B_*D_];
__device__ float g_pq  [B_*AP_];
__device__ int   g_idx [L_*B_];            // decoder input index per (t,b)
__device__ int   g_fo  [B_*L_];            // first occurrence of l in targets[b,:]

// ---------------- generic tiled SGEMM ----------------
// C[M,N] = A[M,K] * B  (+bias per column)
// WT=true : B(k,n) = Bm[n*ldb + k]   (PyTorch weight [N,K], y = x @ W.T)
// WT=false: B(k,n) = Bm[k*ldb + n]   (plain [K,N])
template<int BM,int BN,int TM,int TN,bool WT>
__device__ __forceinline__ void gemm_body(
    const float* __restrict__ A, int lda,
    const float* __restrict__ Bm, int ldb,
    const float* __restrict__ bias,
    float* __restrict__ C, int ldc, int K)
{
    constexpr int BKK = 16;
    constexpr int NT  = (BM/TM)*(BN/TN);
    __shared__ float As[BKK][BM];
    __shared__ float Bs[BKK][BN];
    const int tid = threadIdx.x;
    const int m0 = blockIdx.y*BM, n0 = blockIdx.x*BN;
    const int tc = tid % (BN/TN), tr = tid / (BN/TN);
    float acc[TM][TN];
#pragma unroll
    for (int i=0;i<TM;i++)
#pragma unroll
        for (int j=0;j<TN;j++) acc[i][j]=0.f;

    for (int k0=0;k0<K;k0+=BKK) {
        for (int i=tid;i<BM*BKK;i+=NT) {
            int r=i/BKK, kk=i%BKK;
            As[kk][r] = A[(m0+r)*lda + k0+kk];
        }
        if (WT) {
            for (int i=tid;i<BN*BKK;i+=NT) {
                int n=i/BKK, kk=i%BKK;
                Bs[kk][n] = Bm[(n0+n)*ldb + k0+kk];
            }
        } else {
            for (int i=tid;i<BN*BKK;i+=NT) {
                int kk=i/BN, n=i%BN;
                Bs[kk][n] = Bm[(k0+kk)*ldb + n0+n];
            }
        }
        __syncthreads();
#pragma unroll
        for (int kk=0;kk<BKK;kk++) {
            float a[TM], bb[TN];
#pragma unroll
            for (int i=0;i<TM;i++) a[i]=As[kk][tr*TM+i];
#pragma unroll
            for (int j=0;j<TN;j++) bb[j]=Bs[kk][tc*TN+j];
#pragma unroll
            for (int i=0;i<TM;i++)
#pragma unroll
                for (int j=0;j<TN;j++) acc[i][j] += a[i]*bb[j];
        }
        __syncthreads();
    }
#pragma unroll
    for (int i=0;i<TM;i++) {
        int m = m0 + tr*TM + i;
#pragma unroll
        for (int j=0;j<TN;j++) {
            int n = n0 + tc*TN + j;
            C[m*ldc+n] = acc[i][j] + (bias ? bias[n] : 0.f);
        }
    }
}

template<int BM,int BN,int TM,int TN,bool WT>
__global__ void __launch_bounds__(256) sgemm_k(
    const float* __restrict__ A, int lda,
    const float* __restrict__ Bm, int ldb,
    const float* __restrict__ bias,
    float* __restrict__ C, int ldc, int K)
{
    gemm_body<BM,BN,TM,TN,WT>(A,lda,Bm,ldb,bias,C,ldc,K);
}

// Decoder gate GEMMs fused via blockIdx.z: z=0 -> gh = h@dec_Wh.T, z=1 -> gic = ctx@dec_Wi[:, :H].T
__global__ void __launch_bounds__(256) dec_gates_k(
    const float* __restrict__ dec_Wh, const float* __restrict__ dec_Wi)
{
    if (blockIdx.z == 0)
        gemm_body<32,64,2,4,true>(g_h,  H_, dec_Wh, H_,  nullptr, g_gh,  G3H_, H_);
    else
        gemm_body<32,64,2,4,true>(g_ctx,H_, dec_Wi, 768, nullptr, g_gic, G3H_, H_);
}

// ---------------- small kernels ----------------
__global__ void zero_h_k() {
    int i = blockIdx.x*256 + threadIdx.x;
    g_h[i] = 0.f;
}

__global__ void dense_in_k(const float* __restrict__ in,
                           const float* __restrict__ W_in,
                           const float* __restrict__ b_in)
{
    int i = blockIdx.x*256 + threadIdx.x;     // B*L*D
    int m = i / D_, d = i % D_;
    g_dense[i] = in[m*2]*W_in[d*2] + in[m*2+1]*W_in[d*2+1] + b_in[d];
}

__global__ void masks_k(const int* __restrict__ targets) {
    int b = blockIdx.x, l = threadIdx.x;      // 64 threads
    int fo = L_;
    for (int s=0;s<L_;s++) if (targets[b*L_+s]==l) { fo = s; break; }
    g_fo[b*L_+l] = fo;
    g_idx[l*B_+b] = (l==0) ? 0 : targets[b*L_+l-1];
}

__device__ __forceinline__ float sigmf(float x){ return 1.f/(1.f+expf(-x)); }

__global__ void enc_pointwise_k(const float* __restrict__ bi,
                                const float* __restrict__ bh,
                                const int* __restrict__ lengths, int t)
{
    int i = blockIdx.x*256 + threadIdx.x;     // B*H
    int b = i >> 9, j = i & (H_-1);
    const float* gi = &g_enc_gi[(b*L_+t)*G3H_];
    const float* gh = &g_gh[b*G3H_];
    float ir = gi[j]        + bi[j];
    float iz = gi[j+H_]     + bi[j+H_];
    float in_= gi[j+2*H_]   + bi[j+2*H_];
    float hr = gh[j]        + bh[j];
    float hz = gh[j+H_]     + bh[j+H_];
    float hn = gh[j+2*H_]   + bh[j+2*H_];
    float r = sigmf(ir+hr);
    float z = sigmf(iz+hz);
    float n = tanhf(in_ + r*hn);
    float h = g_h[i];
    float hnew = (1.f-z)*n + z*h;
    g_h[i] = hnew;
    g_enc_out[(b*L_+t)*H_+j] = (t < lengths[b]) ? hnew : 0.f;
}

__global__ void hidden0_k(const int* __restrict__ lengths) {
    int i = blockIdx.x*256 + threadIdx.x;     // B*H
    int b = i >> 9, j = i & (H_-1);
    g_h[i] = g_enc_out[(b*L_ + lengths[b]-1)*H_ + j];
}

__global__ void attn_s2s_k(const float* __restrict__ v,
                           const int* __restrict__ lengths, int t)
{
    int b = blockIdx.x;
    __shared__ float sc[L_];
    int tid = threadIdx.x, lane = tid & 31, w = tid >> 5;
    int len = lengths[b];
    bool tvalid = (t < len);
    const float* qp = &g_q[b*AS_];
    for (int l = w; l < L_; l += 8) {
        const float* kp = &g_enc_keys[(b*L_+l)*AS_];
        float acc = 0.f;
#pragma unroll 4
        for (int a = lane; a < AS_; a += 32)
            acc += tanhf(qp[a] + kp[a]) * v[a];
        for (int o=16;o;o>>=1) acc += __shfl_down_sync(0xffffffffu, acc, o);
        if (lane==0) sc[l] = (tvalid && l < len) ? acc : NEGV;
    }
    __syncthreads();
    if (w == 0) {
        float v0 = sc[lane], v1 = sc[lane+32];
        float m = fmaxf(v0, v1);
        for (int o=16;o;o>>=1) m = fmaxf(m, __shfl_xor_sync(0xffffffffu, m, o));
        float e0 = expf(v0-m), e1 = expf(v1-m);
        float s = e0+e1;
        for (int o=16;o;o>>=1) s += __shfl_xor_sync(0xffffffffu, s, o);
        sc[lane] = e0/s; sc[lane+32] = e1/s;
    }
    __syncthreads();
    for (int j = tid; j < H_; j += 256) {
        float c = 0.f;
#pragma unroll 8
        for (int l=0;l<L_;l++) c += sc[l] * g_enc_out[(b*L_+l)*H_+j];
        g_ctx[b*H_+j] = c;
    }
}

__global__ void dec_pointwise_k(const float* __restrict__ bi,
                                const float* __restrict__ bh, int t)
{
    int i = blockIdx.x*256 + threadIdx.x;     // B*H
    int b = i >> 9, j = i & (H_-1);
    int idx = g_idx[t*B_+b];
    const float* gx = &g_decx_gi[(b*L_+idx)*G3H_];
    const float* gc = &g_gic[b*G3H_];
    const float* gh = &g_gh[b*G3H_];
    float ir = gx[j]      + gc[j]      + bi[j];
    float iz = gx[j+H_]   + gc[j+H_]   + bi[j+H_];
    float in_= gx[j+2*H_] + gc[j+2*H_] + bi[j+2*H_];
    float hr = gh[j]      + bh[j];
    float hz = gh[j+H_]   + bh[j+H_];
    float hn = gh[j+2*H_] + bh[j+2*H_];
    float r = sigmf(ir+hr);
    float z = sigmf(iz+hz);
    float n = tanhf(in_ + r*hn);
    float h = g_h[i];
    g_h[i] = (1.f-z)*n + z*h;
}

__global__ void ptr_attn_k(const float* __restrict__ pv,
                           const int* __restrict__ lengths,
                           float* __restrict__ out_logits,
                           float* __restrict__ out_preds, int t)
{
    int b = blockIdx.x;
    __shared__ float sc[L_];
    int tid = threadIdx.x, lane = tid & 31, w = tid >> 5;
    int len = lengths[b];
    bool tvalid = (t < len);
    const float* qp = &g_pq[b*AP_];
    for (int l = w; l < L_; l += 8) {
        const float* kp = &g_ptr_keys[(b*L_+l)*AP_];
        float acc = 0.f;
#pragma unroll 4
        for (int a = lane; a < AP_; a += 32)
            acc += tanhf(qp[a] + kp[a]) * pv[a];
        for (int o=16;o;o>>=1) acc += __shfl_down_sync(0xffffffffu, acc, o);
        if (lane==0) {
            bool ok = tvalid && (l < len) && (g_fo[b*L_+l] >= t);
            float val = ok ? acc : NEGV;
            sc[l] = val;
            out_logits[(b*L_+t)*L_+l] = val;
        }
    }
    __syncthreads();
    if (w == 0 && out_preds) {
        float v0 = sc[lane], v1 = sc[lane+32];
        float bv; int bidx;
        if (v1 > v0) { bv = v1; bidx = lane+32; } else { bv = v0; bidx = lane; }
        for (int o=16;o;o>>=1) {
            float ov = __shfl_down_sync(0xffffffffu, bv, o);
            int   oi = __shfl_down_sync(0xffffffffu, bidx, o);
            if (ov > bv || (ov == bv && oi < bidx)) { bv = ov; bidx = oi; }
        }
        if (lane == 0) out_preds[b*L_+t] = (float)bidx;
    }
}

// ---------------- host ----------------
static float* symf(const void* sym) {
    void* p = nullptr;
    cudaGetSymbolAddress(&p, sym);
    return (float*)p;
}

extern "C" void kernel_launch(void* const* d_in, const int* in_sizes, int n_in,
                              void* d_out, int out_size)
{
    const float* inputs  = (const float*)d_in[0];
    const int*   lengths = (const int*)  d_in[1];
    const int*   targets = (const int*)  d_in[2];
    const float* W_in    = (const float*)d_in[3];
    const float* b_in    = (const float*)d_in[4];
    const float* enc_Wi  = (const float*)d_in[5];
    const float* enc_Wh  = (const float*)d_in[6];
    const float* enc_bi  = (const float*)d_in[7];
    const float* enc_bh  = (const float*)d_in[8];
    const float* dec_Wi  = (const float*)d_in[9];
    const float* dec_Wh  = (const float*)d_in[10];
    const float* dec_bi  = (const float*)d_in[11];
    const float* dec_bh  = (const float*)d_in[12];
    const float* s2s_Wq  = (const float*)d_in[13];
    const float* s2s_Wk  = (const float*)d_in[14];
    const float* s2s_v   = (const float*)d_in[15];
    const float* W_out   = (const float*)d_in[16];
    const float* b_out   = (const float*)d_in[17];
    const float* ptr_Wq  = (const float*)d_in[18];
    const float* ptr_Wk  = (const float*)d_in[19];
    const float* ptr_v   = (const float*)d_in[20];

    float* out = (float*)d_out;
    float* out_logits = out;
    float* out_preds  = (out_size >= B_*L_*L_ + B_*L_) ? (out + B_*L_*L_) : nullptr;

    float* p_dense    = symf(g_dense);
    float* p_encgi    = symf(g_enc_gi);
    float* p_decxgi   = symf(g_decx_gi);
    float* p_encout   = symf(g_enc_out);
    float* p_enckeys  = symf(g_enc_keys);
    float* p_ptrkeys  = symf(g_ptr_keys);
    float* p_h        = symf(g_h);
    float* p_gh       = symf(g_gh);
    float* p_q        = symf(g_q);
    float* p_dout     = symf(g_dout);
    float* p_pq       = symf(g_pq);

    // ---- one-time precompute ----
    zero_h_k<<<(B_*H_)/256, 256>>>();
    dense_in_k<<<(B_*L_*D_)/256, 256>>>(inputs, W_in, b_in);
    masks_k<<<B_, L_>>>(targets);
    // enc_gi = dense @ enc_Wi.T        [8192,1536] K=256
    sgemm_k<64,64,4,4,true><<<dim3(G3H_/64, (B_*L_)/64), 256>>>(
        p_dense, D_, enc_Wi, D_, nullptr, p_encgi, G3H_, D_);
    // decx_gi = dense @ dec_Wi[:,H:].T [8192,1536] K=256 (weights at column offset H, row stride 768)
    sgemm_k<64,64,4,4,true><<<dim3(G3H_/64, (B_*L_)/64), 256>>>(
        p_dense, D_, dec_Wi + H_, 768, nullptr, p_decxgi, G3H_, D_);
    // ptr_keys = dense @ ptr_Wk        [8192,256] K=256 (plain layout)
    sgemm_k<64,64,4,4,false><<<dim3(AP_/64, (B_*L_)/64), 256>>>(
        p_dense, D_, ptr_Wk, AP_, nullptr, p_ptrkeys, AP_, D_);

    // ---- encoder ----
    for (int t = 0; t < L_; t++) {
        sgemm_k<32,64,2,4,true><<<dim3(G3H_/64, B_/32), 256>>>(
            p_h, H_, enc_Wh, H_, nullptr, p_gh, G3H_, H_);
        enc_pointwise_k<<<(B_*H_)/256, 256>>>(enc_bi, enc_bh, lengths, t);
    }
    hidden0_k<<<(B_*H_)/256, 256>>>(lengths);
    // enc_keys = enc_out @ s2s_Wk      [8192,512] K=512 (plain layout)
    sgemm_k<64,64,4,4,false><<<dim3(AS_/64, (B_*L_)/64), 256>>>(
        p_encout, H_, s2s_Wk, AS_, nullptr, p_enckeys, AS_, H_);

    // ---- decoder ----
    for (int t = 0; t < L_; t++) {
        // q = h @ s2s_Wq  [128,512] K=512
        sgemm_k<32,64,2,4,false><<<dim3(AS_/64, B_/32), 256>>>(
            p_h, H_, s2s_Wq, AS_, nullptr, p_q, AS_, H_);
        attn_s2s_k<<<B_, 256>>>(s2s_v, lengths, t);
        dec_gates_k<<<dim3(G3H_/64, B_/32, 2), 256>>>(dec_Wh, dec_Wi);
        dec_pointwise_k<<<(B_*H_)/256, 256>>>(dec_bi, dec_bh, t);
        // dense_out = h @ W_out.T + b_out  [128,256] K=512
        sgemm_k<32,64,2,4,true><<<dim3(D_/64, B_/32), 256>>>(
            p_h, H_, W_out, H_, b_out, p_dout, D_, H_);
        // pq = dense_out @ ptr_Wq  [128,256] K=256
        sgemm_k<32,64,2,4,false><<<dim3(AP_/64, B_/32), 256>>>(
            p_dout, D_, ptr_Wq, AP_, nullptr, p_pq, AP_, D_);
        ptr_attn_k<<<B_, 256>>>(ptr_v, lengths, out_logits, out_preds, t);
    }
}

// round 4
// speedup vs baseline: 2.3057x; 2.3057x over previous
#include <cuda_runtime.h>
#include <math.h>

#define B_   128
#define L_   64
#define D_   256
#define H_   512
#define AS_  512
#define AP_  256
#define G3H_ 1536
#define NEGV (-1.0e9f)
#define NB   128          // persistent blocks (<= 148 SMs -> co-resident)
#define NT_  256          // threads per block
#define GSTRIDE (NB*NT_)

// ---------------- scratch (device globals; no allocation allowed) ----------------
__device__ float g_dense   [B_*L_*D_];
__device__ float g_enc_gi  [B_*L_*G3H_];
__device__ float g_decx_gi [B_*L_*G3H_];
__device__ float g_enc_out [B_*L_*H_];
__device__ float g_enc_keys[B_*L_*AS_];
__device__ float g_ptr_keys[B_*L_*AP_];
__device__ float g_h   [B_*H_];
__device__ float g_gh  [B_*G3H_];
__device__ float g_gic [B_*G3H_];
__device__ float g_ctx [B_*H_];
__device__ float g_q   [B_*AS_];
__device__ float g_dout[B_*D_];
__device__ float g_pq  [B_*AP_];
__device__ int   g_idx [L_*B_];
__device__ int   g_fo  [B_*L_];
__device__ unsigned long long g_cnt;   // grid-barrier counter (monotonic)

// ---------------- helpers ----------------
__device__ __forceinline__ unsigned long long pk2(float x, float y) {
    unsigned long long r;
    asm("mov.b64 %0, {%1, %2};" : "=l"(r) : "f"(x), "f"(y));
    return r;
}
__device__ __forceinline__ void upk2(unsigned long long v, float& x, float& y) {
    asm("mov.b64 {%0, %1}, %2;" : "=f"(x), "=f"(y) : "l"(v));
}
__device__ __forceinline__ unsigned long long fma2(unsigned long long a,
                                                   unsigned long long b,
                                                   unsigned long long c) {
    unsigned long long d;
    asm("fma.rn.f32x2 %0, %1, %2, %3;" : "=l"(d) : "l"(a), "l"(b), "l"(c));
    return d;
}
__device__ __forceinline__ float tanhax(float x) {
    float y; asm("tanh.approx.f32 %0, %1;" : "=f"(y) : "f"(x)); return y;
}
__device__ __forceinline__ float ex2ax(float x) {
    float y; asm("ex2.approx.f32 %0, %1;" : "=f"(y) : "f"(x)); return y;
}
__device__ __forceinline__ float expax(float x) { return ex2ax(x * 1.4426950408889634f); }
__device__ __forceinline__ float sigax(float x) { return 0.5f * tanhax(0.5f * x) + 0.5f; }

__device__ __forceinline__ void bar_half(int hb) {
    asm volatile("bar.sync %0, 128;" :: "r"(1 + hb) : "memory");
}

// software grid barrier: monotonic counter; all NB blocks co-resident
__device__ __forceinline__ void gsync() {
    __syncthreads();
    if (threadIdx.x == 0) {
        __threadfence();
        unsigned long long old = atomicAdd(&g_cnt, 1ULL);
        unsigned long long target = (old - (old & (unsigned long long)(NB - 1))) + NB;
        while (*((volatile unsigned long long*)&g_cnt) < target) { }
        __threadfence();
    }
    __syncthreads();
}

// ---------------- 32x64 tile GEMM on a 128-thread half-block ----------------
// C[m0:m0+32, n0:n0+64] = A[m0:.., :K] * B (+bias), fp32, packed f32x2 FMA.
// WT=true : B(k,n) = Bm[n*ldb + k]   (y = x @ W.T, torch layout)
// WT=false: B(k,n) = Bm[k*ldb + n]
template<bool WT>
__device__ __forceinline__ void tileg(
    const float* __restrict__ A, int lda,
    const float* __restrict__ Bm, int ldb,
    const float* __restrict__ bias,
    float* __restrict__ C, int ldc, int K,
    int m0, int n0, int t, int hb,
    float (*As)[32], float (*Bs)[64])
{
    const int ar = t >> 2, ac = t & 3;        // A loader: row, k-quad
    const int tr4 = (t >> 4) << 2;            // compute: 4 rows
    const int tc4 = (t & 15) << 2;            // compute: 4 cols
    unsigned long long acc00 = 0, acc01 = 0, acc10 = 0, acc11 = 0;
    unsigned long long acc20 = 0, acc21 = 0, acc30 = 0, acc31 = 0;

    for (int k0 = 0; k0 < K; k0 += 16) {
        float4 va = *(const float4*)(A + (m0 + ar) * lda + k0 + ac * 4);
        As[ac*4+0][ar] = va.x; As[ac*4+1][ar] = va.y;
        As[ac*4+2][ar] = va.z; As[ac*4+3][ar] = va.w;
        if (WT) {
#pragma unroll
            for (int rep = 0; rep < 2; rep++) {
                int li = t + rep * 128;
                int n = li >> 2, c = li & 3;
                float4 vb = *(const float4*)(Bm + (n0 + n) * ldb + k0 + c * 4);
                Bs[c*4+0][n] = vb.x; Bs[c*4+1][n] = vb.y;
                Bs[c*4+2][n] = vb.z; Bs[c*4+3][n] = vb.w;
            }
        } else {
#pragma unroll
            for (int rep = 0; rep < 2; rep++) {
                int li = t + rep * 128;
                int kk = li >> 4, q = li & 15;
                *(float4*)(&Bs[kk][q*4]) =
                    *(const float4*)(Bm + (k0 + kk) * ldb + n0 + q * 4);
            }
        }
        bar_half(hb);
#pragma unroll
        for (int kk = 0; kk < 16; kk++) {
            float4 a4 = *(const float4*)(&As[kk][tr4]);
            float4 b4 = *(const float4*)(&Bs[kk][tc4]);
            unsigned long long b01 = pk2(b4.x, b4.y);
            unsigned long long b23 = pk2(b4.z, b4.w);
            unsigned long long ad;
            ad = pk2(a4.x, a4.x); acc00 = fma2(ad, b01, acc00); acc01 = fma2(ad, b23, acc01);
            ad = pk2(a4.y, a4.y); acc10 = fma2(ad, b01, acc10); acc11 = fma2(ad, b23, acc11);
            ad = pk2(a4.z, a4.z); acc20 = fma2(ad, b01, acc20); acc21 = fma2(ad, b23, acc21);
            ad = pk2(a4.w, a4.w); acc30 = fma2(ad, b01, acc30); acc31 = fma2(ad, b23, acc31);
        }
        bar_half(hb);
    }

    float bx0 = 0.f, bx1 = 0.f, bx2 = 0.f, bx3 = 0.f;
    if (bias) { bx0 = bias[n0+tc4]; bx1 = bias[n0+tc4+1]; bx2 = bias[n0+tc4+2]; bx3 = bias[n0+tc4+3]; }
    unsigned long long accs[4][2] = {{acc00,acc01},{acc10,acc11},{acc20,acc21},{acc30,acc31}};
#pragma unroll
    for (int i = 0; i < 4; i++) {
        float x0,x1,x2,x3;
        upk2(accs[i][0], x0, x1); upk2(accs[i][1], x2, x3);
        float4 o; o.x = x0+bx0; o.y = x1+bx1; o.z = x2+bx2; o.w = x3+bx3;
        *(float4*)(C + (m0 + tr4 + i) * ldc + n0 + tc4) = o;
    }
}

// ---------------- attention jobs (128-thread half-block each) ----------------
__device__ __forceinline__ void attn_s2s_job(
    int b, int t, int t128, int hb, float* sc,
    const int* __restrict__ lengths, const float* __restrict__ v)
{
    const int w = t128 >> 5, lane = t128 & 31;
    const int len = lengths[b];
    const float* qp = g_q + b * AS_;
    const float* kb = g_enc_keys + b * L_ * AS_;
#pragma unroll
    for (int l = w; l < L_; l += 4) {
        const float* kp = kb + l * AS_;
        float acc = 0.f;
#pragma unroll 4
        for (int a = lane; a < AS_; a += 32)
            acc += tanhax(qp[a] + kp[a]) * v[a];
        for (int o = 16; o; o >>= 1) acc += __shfl_down_sync(0xffffffffu, acc, o);
        if (lane == 0) sc[l] = (t < len && l < len) ? acc : NEGV;
    }
    bar_half(hb);
    if (w == 0) {
        float v0 = sc[lane], v1 = sc[lane + 32];
        float m = fmaxf(v0, v1);
        for (int o = 16; o; o >>= 1) m = fmaxf(m, __shfl_xor_sync(0xffffffffu, m, o));
        float e0 = expax(v0 - m), e1 = expax(v1 - m);
        float s = e0 + e1;
        for (int o = 16; o; o >>= 1) s += __shfl_xor_sync(0xffffffffu, s, o);
        float inv = 1.f / s;
        sc[lane] = e0 * inv; sc[lane + 32] = e1 * inv;
    }
    bar_half(hb);
#pragma unroll
    for (int r = 0; r < 4; r++) {
        int j = t128 + r * 128;
        float c = 0.f;
#pragma unroll 8
        for (int l = 0; l < L_; l++)
            c += sc[l] * g_enc_out[(b * L_ + l) * H_ + j];
        g_ctx[b * H_ + j] = c;
    }
}

__device__ __forceinline__ void ptr_attn_job(
    int b, int tt, int t128, int hb, float* sc,
    const int* __restrict__ lengths, const float* __restrict__ pv,
    float* __restrict__ out_logits, float* __restrict__ out_preds)
{
    const int w = t128 >> 5, lane = t128 & 31;
    const int len = lengths[b];
    const float* qp = g_pq + b * AP_;
    const float* kb = g_ptr_keys + b * L_ * AP_;
#pragma unroll
    for (int l = w; l < L_; l += 4) {
        const float* kp = kb + l * AP_;
        float acc = 0.f;
#pragma unroll 4
        for (int a = lane; a < AP_; a += 32)
            acc += tanhax(qp[a] + kp[a]) * pv[a];
        for (int o = 16; o; o >>= 1) acc += __shfl_down_sync(0xffffffffu, acc, o);
        if (lane == 0) {
            bool ok = (tt < len) && (l < len) && (g_fo[b * L_ + l] >= tt);
            float val = ok ? acc : NEGV;
            sc[l] = val;
            out_logits[(b * L_ + tt) * L_ + l] = val;
        }
    }
    bar_half(hb);
    if (w == 0 && out_preds) {
        float v0 = sc[lane], v1 = sc[lane + 32];
        float bv; int bidx;
        if (v1 > v0) { bv = v1; bidx = lane + 32; } else { bv = v0; bidx = lane; }
        for (int o = 16; o; o >>= 1) {
            float ov = __shfl_down_sync(0xffffffffu, bv, o);
            int   oi = __shfl_down_sync(0xffffffffu, bidx, o);
            if (ov > bv || (ov == bv && oi < bidx)) { bv = ov; bidx = oi; }
        }
        if (lane == 0) out_preds[b * L_ + tt] = (float)bidx;
    }
}

// ---------------- the single persistent kernel ----------------
__global__ void __launch_bounds__(NT_) seq_kernel(
    const float* __restrict__ inputs, const int* __restrict__ lengths,
    const int* __restrict__ targets,
    const float* __restrict__ W_in, const float* __restrict__ b_in,
    const float* __restrict__ enc_Wi, const float* __restrict__ enc_Wh,
    const float* __restrict__ enc_bi, const float* __restrict__ enc_bh,
    const float* __restrict__ dec_Wi, const float* __restrict__ dec_Wh,
    const float* __restrict__ dec_bi, const float* __restrict__ dec_bh,
    const float* __restrict__ s2s_Wq, const float* __restrict__ s2s_Wk,
    const float* __restrict__ s2s_v,
    const float* __restrict__ W_out, const float* __restrict__ b_out,
    const float* __restrict__ ptr_Wq, const float* __restrict__ ptr_Wk,
    const float* __restrict__ ptr_v,
    float* __restrict__ out_logits, float* __restrict__ out_preds)
{
    __shared__ float As[2][16][32];
    __shared__ float Bs[2][16][64];
    __shared__ float scr[2][64];

    const int tid  = threadIdx.x;
    const int bid  = blockIdx.x;
    const int hb   = tid >> 7;
    const int t128 = tid & 127;
    const int slot = bid + hb * NB;          // 0..255
    const int gtid = bid * NT_ + tid;

    // ---- phase 0: dense_inputs, masks/idx, zero h ----
    for (int i = gtid; i < B_ * L_ * D_; i += GSTRIDE) {
        int m = i >> 8, d = i & 255;
        g_dense[i] = inputs[m*2] * W_in[d*2] + inputs[m*2+1] * W_in[d*2+1] + b_in[d];
    }
    for (int i = gtid; i < B_ * L_; i += GSTRIDE) {
        int b = i >> 6, l = i & 63;
        int fo = L_;
        for (int s = 0; s < L_; s++) if (targets[b*L_+s] == l) { fo = s; break; }
        g_fo[b*L_+l] = fo;
        g_idx[l*B_+b] = (l == 0) ? 0 : targets[b*L_ + l - 1];
    }
    for (int i = gtid; i < B_ * H_; i += GSTRIDE) g_h[i] = 0.f;
    gsync();

    // ---- precompute GEMMs: enc_gi, decx_gi, ptr_keys (13312 tile jobs) ----
    for (int j = slot; j < 13312; j += 256) {
        if (j < 6144) {
            int mi = j / 24, ni = j - mi * 24;
            tileg<true>(g_dense, D_, enc_Wi, D_, nullptr, g_enc_gi, G3H_, D_,
                        mi*32, ni*64, t128, hb, As[hb], Bs[hb]);
        } else if (j < 12288) {
            int j2 = j - 6144; int mi = j2 / 24, ni = j2 - mi * 24;
            tileg<true>(g_dense, D_, dec_Wi + H_, H_ + D_, nullptr, g_decx_gi, G3H_, D_,
                        mi*32, ni*64, t128, hb, As[hb], Bs[hb]);
        } else {
            int j2 = j - 12288; int mi = j2 >> 2, ni = j2 & 3;
            tileg<false>(g_dense, D_, ptr_Wk, AP_, nullptr, g_ptr_keys, AP_, D_,
                         mi*32, ni*64, t128, hb, As[hb], Bs[hb]);
        }
    }
    gsync();

    // ---- encoder recurrence ----
    for (int t = 0; t < L_; t++) {
        for (int j = slot; j < 96; j += 256) {
            int mi = j / 24, ni = j - mi * 24;
            tileg<true>(g_h, H_, enc_Wh, H_, nullptr, g_gh, G3H_, H_,
                        mi*32, ni*64, t128, hb, As[hb], Bs[hb]);
        }
        gsync();
        for (int i = gtid; i < B_ * H_; i += GSTRIDE) {
            int b = i >> 9, jj = i & 511;
            const float* gi = g_enc_gi + (b*L_ + t) * G3H_;
            const float* gh = g_gh + b * G3H_;
            float r  = sigax(gi[jj]        + enc_bi[jj]        + gh[jj]        + enc_bh[jj]);
            float z  = sigax(gi[jj+H_]     + enc_bi[jj+H_]     + gh[jj+H_]     + enc_bh[jj+H_]);
            float n  = tanhax(gi[jj+2*H_]  + enc_bi[jj+2*H_] +
                              r * (gh[jj+2*H_] + enc_bh[jj+2*H_]));
            float h  = g_h[i];
            float hn = (1.f - z) * n + z * h;
            g_h[i] = hn;
            g_enc_out[(b*L_ + t) * H_ + jj] = (t < lengths[b]) ? hn : 0.f;
        }
        gsync();
    }

    // ---- enc_keys (2048 tiles) + hidden0 gather (8 jobs) ----
    for (int j = slot; j < 2056; j += 256) {
        if (j < 2048) {
            int mi = j >> 3, ni = j & 7;
            tileg<false>(g_enc_out, H_, s2s_Wk, AS_, nullptr, g_enc_keys, AS_, H_,
                         mi*32, ni*64, t128, hb, As[hb], Bs[hb]);
        } else {
            int jb = j - 2048;
            for (int e = t128; e < 8192; e += 128) {
                int i = jb * 8192 + e;
                int b = i >> 9, jj = i & 511;
                g_h[i] = g_enc_out[(b*L_ + lengths[b] - 1) * H_ + jj];
            }
        }
    }
    gsync();

    // ---- decoder: software-pipelined, 4 barriers/step ----
    for (int t = 0; t <= L_; t++) {
        const int tp = t - 1;
        // P1: q_t (32 tiles) ; dout_{t-1} (16 tiles)  [both read current h]
        {
            int nq = (t < L_) ? 32 : 0, nd = (t > 0) ? 16 : 0;
            for (int j = slot; j < nq + nd; j += 256) {
                if (j < nq) {
                    int mi = j >> 3, ni = j & 7;
                    tileg<false>(g_h, H_, s2s_Wq, AS_, nullptr, g_q, AS_, H_,
                                 mi*32, ni*64, t128, hb, As[hb], Bs[hb]);
                } else {
                    int j2 = j - nq; int mi = j2 >> 2, ni = j2 & 3;
                    tileg<true>(g_h, H_, W_out, H_, b_out, g_dout, D_, H_,
                                mi*32, ni*64, t128, hb, As[hb], Bs[hb]);
                }
            }
            gsync();
        }
        // P2: pq_{t-1} (16 tiles) ; s2s attention_t (128 jobs)
        {
            int np = (t > 0) ? 16 : 0, na = (t < L_) ? 128 : 0;
            for (int j = slot; j < np + na; j += 256) {
                if (j < np) {
                    int j2 = j; int mi = j2 >> 2, ni = j2 & 3;
                    tileg<false>(g_dout, D_, ptr_Wq, AP_, nullptr, g_pq, AP_, D_,
                                 mi*32, ni*64, t128, hb, As[hb], Bs[hb]);
                } else {
                    attn_s2s_job(j - np, t, t128, hb, scr[hb], lengths, s2s_v);
                }
            }
            gsync();
        }
        // P3: gh_t + gic_t (192 tiles) ; ptr attention_{t-1} (128 jobs)
        {
            int ng = (t < L_) ? 192 : 0, nf = (t > 0) ? 128 : 0;
            for (int j = slot; j < ng + nf; j += 256) {
                if (j < ng) {
                    if (j < 96) {
                        int mi = j / 24, ni = j - mi * 24;
                        tileg<true>(g_h, H_, dec_Wh, H_, nullptr, g_gh, G3H_, H_,
                                    mi*32, ni*64, t128, hb, As[hb], Bs[hb]);
                    } else {
                        int j2 = j - 96; int mi = j2 / 24, ni = j2 - mi * 24;
                        tileg<true>(g_ctx, H_, dec_Wi, H_ + D_, nullptr, g_gic, G3H_, H_,
                                    mi*32, ni*64, t128, hb, As[hb], Bs[hb]);
                    }
                } else {
                    ptr_attn_job(j - ng, tp, t128, hb, scr[hb], lengths, ptr_v,
                                 out_logits, out_preds);
                }
            }
            gsync();
        }
        // P4: GRU gate update -> h_{t+1}
        if (t < L_) {
            for (int i = gtid; i < B_ * H_; i += GSTRIDE) {
                int b = i >> 9, jj = i & 511;
                int ix = g_idx[t*B_ + b];
                const float* gx = g_decx_gi + (b*L_ + ix) * G3H_;
                const float* gc = g_gic + b * G3H_;
                const float* gh = g_gh  + b * G3H_;
                float r = sigax(gx[jj]      + gc[jj]      + dec_bi[jj]      + gh[jj]      + dec_bh[jj]);
                float z = sigax(gx[jj+H_]   + gc[jj+H_]   + dec_bi[jj+H_]   + gh[jj+H_]   + dec_bh[jj+H_]);
                float n = tanhax(gx[jj+2*H_] + gc[jj+2*H_] + dec_bi[jj+2*H_] +
                                 r * (gh[jj+2*H_] + dec_bh[jj+2*H_]));
                float h = g_h[i];
                g_h[i] = (1.f - z) * n + z * h;
            }
        }
        gsync();
    }
}

// ---------------- host ----------------
extern "C" void kernel_launch(void* const* d_in, const int* in_sizes, int n_in,
                              void* d_out, int out_size)
{
    const float* inputs  = (const float*)d_in[0];
    const int*   lengths = (const int*)  d_in[1];
    const int*   targets = (const int*)  d_in[2];
    const float* W_in    = (const float*)d_in[3];
    const float* b_in    = (const float*)d_in[4];
    const float* enc_Wi  = (const float*)d_in[5];
    const float* enc_Wh  = (const float*)d_in[6];
    const float* enc_bi  = (const float*)d_in[7];
    const float* enc_bh  = (const float*)d_in[8];
    const float* dec_Wi  = (const float*)d_in[9];
    const float* dec_Wh  = (const float*)d_in[10];
    const float* dec_bi  = (const float*)d_in[11];
    const float* dec_bh  = (const float*)d_in[12];
    const float* s2s_Wq  = (const float*)d_in[13];
    const float* s2s_Wk  = (const float*)d_in[14];
    const float* s2s_v   = (const float*)d_in[15];
    const float* W_out   = (const float*)d_in[16];
    const float* b_out   = (const float*)d_in[17];
    const float* ptr_Wq  = (const float*)d_in[18];
    const float* ptr_Wk  = (const float*)d_in[19];
    const float* ptr_v   = (const float*)d_in[20];

    float* out = (float*)d_out;
    float* out_logits = out;
    float* out_preds  = (out_size >= B_*L_*L_ + B_*L_) ? (out + B_*L_*L_) : nullptr;

    seq_kernel<<<NB, NT_>>>(inputs, lengths, targets, W_in, b_in,
                            enc_Wi, enc_Wh, enc_bi, enc_bh,
                            dec_Wi, dec_Wh, dec_bi, dec_bh,
                            s2s_Wq, s2s_Wk, s2s_v, W_out, b_out,
                            ptr_Wq, ptr_Wk, ptr_v,
                            out_logits, out_preds);
}

// round 6
// speedup vs baseline: 3.0098x; 1.3054x over previous
#include <cuda_runtime.h>
#include <math.h>

#define B_   128
#define L_   64
#define D_   256
#define H_   512
#define AS_  512
#define AP_  256
#define G3H_ 1536
#define NEGV (-1.0e9f)
#define NB   128          // persistent blocks (<=148 SMs -> co-resident)
#define NT_  512          // threads per block (4 units of 128)
#define NU   4            // GEMM units per block
#define NSLOT (NB*NU)     // 512 parallel job units
#define GSTRIDE (NB*NT_)

// ---------------- scratch (device globals; no allocation allowed) ----------------
__device__ float g_dense   [B_*L_*D_];
__device__ float g_enc_gi  [B_*L_*G3H_];
__device__ float g_decx_gi [B_*L_*G3H_];
__device__ float g_enc_out [B_*L_*H_];
__device__ float g_enc_keys[B_*L_*AS_];
__device__ float g_ptr_keys[B_*L_*AP_];
__device__ float g_h    [B_*H_];
__device__ float g_gh   [B_*G3H_];
__device__ float g_gh2  [B_*G3H_];
__device__ float g_gic  [B_*G3H_];
__device__ float g_gic2 [B_*G3H_];
__device__ float g_ctx  [B_*H_];
__device__ float g_q    [B_*AS_];
__device__ float g_q2   [B_*AS_];
__device__ float g_dout [B_*D_];
__device__ float g_dout2[B_*D_];
__device__ float g_pq   [B_*AP_];
__device__ int   g_idx  [L_*B_];
__device__ int   g_fo   [B_*L_];
__device__ unsigned long long g_cnt;

// ---------------- helpers ----------------
typedef unsigned long long ull;
__device__ __forceinline__ ull pk2(float x, float y) {
    ull r; asm("mov.b64 %0, {%1, %2};" : "=l"(r) : "f"(x), "f"(y)); return r;
}
__device__ __forceinline__ void upk2(ull v, float& x, float& y) {
    asm("mov.b64 {%0, %1}, %2;" : "=f"(x), "=f"(y) : "l"(v));
}
__device__ __forceinline__ ull fma2(ull a, ull b, ull c) {
    ull d; asm("fma.rn.f32x2 %0, %1, %2, %3;" : "=l"(d) : "l"(a), "l"(b), "l"(c));
    return d;
}
__device__ __forceinline__ float tanhax(float x) {
    float y; asm("tanh.approx.f32 %0, %1;" : "=f"(y) : "f"(x)); return y;
}
__device__ __forceinline__ float ex2ax(float x) {
    float y; asm("ex2.approx.f32 %0, %1;" : "=f"(y) : "f"(x)); return y;
}
__device__ __forceinline__ float expax(float x) { return ex2ax(x * 1.4426950408889634f); }
__device__ __forceinline__ float sigax(float x) { return 0.5f * tanhax(0.5f * x) + 0.5f; }

__device__ __forceinline__ void bar_u(int u) {
    asm volatile("bar.sync %0, 128;" :: "r"(1 + u) : "memory");
}

__device__ __forceinline__ void gsync() {
    __syncthreads();
    if (threadIdx.x == 0) {
        __threadfence();
        ull old = atomicAdd(&g_cnt, 1ULL);
        ull target = (old - (old & (ull)(NB - 1))) + NB;
        while (*((volatile ull*)&g_cnt) < target) { }
        __threadfence();
    }
    __syncthreads();
}

// ---------------- 32x64 tile GEMM on a 128-thread unit ----------------
// C[m0:+32, n0:+64] = (A+A2)[m0:+32, kb:ke] * B (+bias), packed f32x2 FMA.
// A staged in smem as duplicated f32x2 pairs -> zero-MOV inner loop.
// WT=true : B(k,n) = Bm[n*ldb+k] ; WT=false: B(k,n) = Bm[k*ldb+n]
template<bool WT>
__device__ __forceinline__ void tileg(
    const float* __restrict__ A, const float* __restrict__ A2, int lda,
    const float* __restrict__ Bm, int ldb,
    const float* __restrict__ bias,
    float* __restrict__ C, int ldc, int kb, int ke,
    int m0, int n0, int t, int u,
    ull (*Asd)[32], float (*Bs)[68])
{
    const int ar = t >> 2, ac = t & 3;
    const int tr4 = (t >> 4) << 2;
    const int tc4 = (t & 15) << 2;
    ull acc00 = 0, acc01 = 0, acc10 = 0, acc11 = 0;
    ull acc20 = 0, acc21 = 0, acc30 = 0, acc31 = 0;

    for (int k0 = kb; k0 < ke; k0 += 16) {
        float4 va = *(const float4*)(A + (m0 + ar) * lda + k0 + ac * 4);
        if (A2) {
            float4 v2 = *(const float4*)(A2 + (m0 + ar) * lda + k0 + ac * 4);
            va.x += v2.x; va.y += v2.y; va.z += v2.z; va.w += v2.w;
        }
        Asd[ac*4+0][ar] = pk2(va.x, va.x);
        Asd[ac*4+1][ar] = pk2(va.y, va.y);
        Asd[ac*4+2][ar] = pk2(va.z, va.z);
        Asd[ac*4+3][ar] = pk2(va.w, va.w);
        if (WT) {
#pragma unroll
            for (int rep = 0; rep < 2; rep++) {
                int li = t + rep * 128;
                int n = li >> 2, c = li & 3;
                float4 vb = *(const float4*)(Bm + (n0 + n) * ldb + k0 + c * 4);
                Bs[c*4+0][n] = vb.x; Bs[c*4+1][n] = vb.y;
                Bs[c*4+2][n] = vb.z; Bs[c*4+3][n] = vb.w;
            }
        } else {
#pragma unroll
            for (int rep = 0; rep < 2; rep++) {
                int li = t + rep * 128;
                int kk = li >> 4, q = li & 15;
                *(float4*)(&Bs[kk][q*4]) =
                    *(const float4*)(Bm + (k0 + kk) * ldb + n0 + q * 4);
            }
        }
        bar_u(u);
#pragma unroll
        for (int kk = 0; kk < 16; kk++) {
            const ull* ap = &Asd[kk][tr4];
            ull a0 = ap[0], a1 = ap[1], a2 = ap[2], a3 = ap[3];
            ull b01 = *(const ull*)&Bs[kk][tc4];
            ull b23 = *(const ull*)&Bs[kk][tc4+2];
            acc00 = fma2(a0, b01, acc00); acc01 = fma2(a0, b23, acc01);
            acc10 = fma2(a1, b01, acc10); acc11 = fma2(a1, b23, acc11);
            acc20 = fma2(a2, b01, acc20); acc21 = fma2(a2, b23, acc21);
            acc30 = fma2(a3, b01, acc30); acc31 = fma2(a3, b23, acc31);
        }
        bar_u(u);
    }

    float bx0 = 0.f, bx1 = 0.f, bx2 = 0.f, bx3 = 0.f;
    if (bias) { bx0 = bias[n0+tc4]; bx1 = bias[n0+tc4+1]; bx2 = bias[n0+tc4+2]; bx3 = bias[n0+tc4+3]; }
    ull accs[4][2] = {{acc00,acc01},{acc10,acc11},{acc20,acc21},{acc30,acc31}};
#pragma unroll
    for (int i = 0; i < 4; i++) {
        float x0,x1,x2,x3;
        upk2(accs[i][0], x0, x1); upk2(accs[i][1], x2, x3);
        float4 o; o.x = x0+bx0; o.y = x1+bx1; o.z = x2+bx2; o.w = x3+bx3;
        *(float4*)(C + (m0 + tr4 + i) * ldc + n0 + tc4) = o;
    }
}

// ---------------- attention jobs (128-thread unit each) ----------------
__device__ __forceinline__ void attn_s2s_job(
    int b, int t, int t128, int u, float* sc,
    const int* __restrict__ lengths, const float* __restrict__ v)
{
    const int w = t128 >> 5, lane = t128 & 31;
    const int len = lengths[b];
    const float* qp  = g_q  + b * AS_;
    const float* qp2 = g_q2 + b * AS_;
    const float* kb = g_enc_keys + b * L_ * AS_;
#pragma unroll
    for (int l = w; l < L_; l += 4) {
        const float* kp = kb + l * AS_;
        float acc = 0.f;
#pragma unroll 4
        for (int a = lane; a < AS_; a += 32)
            acc += tanhax(qp[a] + qp2[a] + kp[a]) * v[a];
        for (int o = 16; o; o >>= 1) acc += __shfl_down_sync(0xffffffffu, acc, o);
        if (lane == 0) sc[l] = (t < len && l < len) ? acc : NEGV;
    }
    bar_u(u);
    if (w == 0) {
        float v0 = sc[lane], v1 = sc[lane + 32];
        float m = fmaxf(v0, v1);
        for (int o = 16; o; o >>= 1) m = fmaxf(m, __shfl_xor_sync(0xffffffffu, m, o));
        float e0 = expax(v0 - m), e1 = expax(v1 - m);
        float s = e0 + e1;
        for (int o = 16; o; o >>= 1) s += __shfl_xor_sync(0xffffffffu, s, o);
        float inv = 1.f / s;
        sc[lane] = e0 * inv; sc[lane + 32] = e1 * inv;
    }
    bar_u(u);
#pragma unroll
    for (int r = 0; r < 4; r++) {
        int j = t128 + r * 128;
        float c = 0.f;
#pragma unroll 8
        for (int l = 0; l < L_; l++)
            c += sc[l] * g_enc_out[(b * L_ + l) * H_ + j];
        g_ctx[b * H_ + j] = c;
    }
}

__device__ __forceinline__ void ptr_attn_job(
    int b, int tt, int t128, int u, float* sc,
    const int* __restrict__ lengths, const float* __restrict__ pv,
    float* __restrict__ out_logits, float* __restrict__ out_preds)
{
    const int w = t128 >> 5, lane = t128 & 31;
    const int len = lengths[b];
    const float* qp = g_pq + b * AP_;
    const float* kb = g_ptr_keys + b * L_ * AP_;
#pragma unroll
    for (int l = w; l < L_; l += 4) {
        const float* kp = kb + l * AP_;
        float acc = 0.f;
#pragma unroll 4
        for (int a = lane; a < AP_; a += 32)
            acc += tanhax(qp[a] + kp[a]) * pv[a];
        for (int o = 16; o; o >>= 1) acc += __shfl_down_sync(0xffffffffu, acc, o);
        if (lane == 0) {
            bool ok = (tt < len) && (l < len) && (g_fo[b * L_ + l] >= tt);
            float val = ok ? acc : NEGV;
            sc[l] = val;
            out_logits[(b * L_ + tt) * L_ + l] = val;
        }
    }
    bar_u(u);
    if (w == 0 && out_preds) {
        float v0 = sc[lane], v1 = sc[lane + 32];
        float bv; int bidx;
        if (v1 > v0) { bv = v1; bidx = lane + 32; } else { bv = v0; bidx = lane; }
        for (int o = 16; o; o >>= 1) {
            float ov = __shfl_down_sync(0xffffffffu, bv, o);
            int   oi = __shfl_down_sync(0xffffffffu, bidx, o);
            if (ov > bv || (ov == bv && oi < bidx)) { bv = ov; bidx = oi; }
        }
        if (lane == 0) out_preds[b * L_ + tt] = (float)bidx;
    }
}

// ---------------- the single persistent kernel ----------------
__global__ void __launch_bounds__(NT_, 1) seq_kernel(
    const float* __restrict__ inputs, const int* __restrict__ lengths,
    const int* __restrict__ targets,
    const float* __restrict__ W_in, const float* __restrict__ b_in,
    const float* __restrict__ enc_Wi, const float* __restrict__ enc_Wh,
    const float* __restrict__ enc_bi, const float* __restrict__ enc_bh,
    const float* __restrict__ dec_Wi, const float* __restrict__ dec_Wh,
    const float* __restrict__ dec_bi, const float* __restrict__ dec_bh,
    const float* __restrict__ s2s_Wq, const float* __restrict__ s2s_Wk,
    const float* __restrict__ s2s_v,
    const float* __restrict__ W_out, const float* __restrict__ b_out,
    const float* __restrict__ ptr_Wq, const float* __restrict__ ptr_Wk,
    const float* __restrict__ ptr_v,
    float* __restrict__ out_logits, float* __restrict__ out_preds)
{
    __shared__ ull   Asd[NU][16][32];
    __shared__ float Bs [NU][16][68];
    __shared__ float scr[NU][64];

    const int tid  = threadIdx.x;
    const int bid  = blockIdx.x;
    const int u    = tid >> 7;               // unit 0..3
    const int t128 = tid & 127;
    const int slot = bid + u * NB;           // 0..511
    const int gtid = bid * NT_ + tid;

    // ---- phase 0: dense_inputs, masks/idx, zero h ----
    for (int i = gtid; i < B_ * L_ * D_; i += GSTRIDE) {
        int m = i >> 8, d = i & 255;
        g_dense[i] = inputs[m*2] * W_in[d*2] + inputs[m*2+1] * W_in[d*2+1] + b_in[d];
    }
    for (int i = gtid; i < B_ * L_; i += GSTRIDE) {
        int b = i >> 6, l = i & 63;
        int fo = L_;
        for (int s = 0; s < L_; s++) if (targets[b*L_+s] == l) { fo = s; break; }
        g_fo[b*L_+l] = fo;
        g_idx[l*B_+b] = (l == 0) ? 0 : targets[b*L_ + l - 1];
    }
    for (int i = gtid; i < B_ * H_; i += GSTRIDE) g_h[i] = 0.f;
    gsync();

    // ---- precompute GEMMs: enc_gi, decx_gi, ptr_keys (13312 tile jobs, K=256) ----
    for (int j = slot; j < 13312; j += NSLOT) {
        if (j < 6144) {
            int mi = j / 24, ni = j - mi * 24;
            tileg<true>(g_dense, nullptr, D_, enc_Wi, D_, nullptr, g_enc_gi, G3H_,
                        0, D_, mi*32, ni*64, t128, u, Asd[u], Bs[u]);
        } else if (j < 12288) {
            int j2 = j - 6144; int mi = j2 / 24, ni = j2 - mi * 24;
            tileg<true>(g_dense, nullptr, D_, dec_Wi + H_, H_ + D_, nullptr, g_decx_gi, G3H_,
                        0, D_, mi*32, ni*64, t128, u, Asd[u], Bs[u]);
        } else {
            int j2 = j - 12288; int mi = j2 >> 2, ni = j2 & 3;
            tileg<false>(g_dense, nullptr, D_, ptr_Wk, AP_, nullptr, g_ptr_keys, AP_,
                         0, D_, mi*32, ni*64, t128, u, Asd[u], Bs[u]);
        }
    }
    gsync();

    // ---- encoder recurrence: gh K-split x4 (384 jobs, 1 wave) ----
    float* encbuf[4] = { g_gh, g_gh2, g_gic, g_gic2 };
    for (int t = 0; t < L_; t++) {
        for (int j = slot; j < 384; j += NSLOT) {
            int tile = j >> 2, ks = j & 3;
            int mi = tile / 24, ni = tile - mi * 24;
            tileg<true>(g_h, nullptr, H_, enc_Wh, H_, nullptr, encbuf[ks], G3H_,
                        ks*128, ks*128+128, mi*32, ni*64, t128, u, Asd[u], Bs[u]);
        }
        gsync();
        for (int i = gtid; i < B_ * H_; i += GSTRIDE) {
            int b = i >> 9, jj = i & 511;
            const float* gi = g_enc_gi + (b*L_ + t) * G3H_;
            int base = b * G3H_;
            float s0 = g_gh[base+jj]      + g_gh2[base+jj]      + g_gic[base+jj]      + g_gic2[base+jj];
            float s1 = g_gh[base+jj+H_]   + g_gh2[base+jj+H_]   + g_gic[base+jj+H_]   + g_gic2[base+jj+H_];
            float s2 = g_gh[base+jj+2*H_] + g_gh2[base+jj+2*H_] + g_gic[base+jj+2*H_] + g_gic2[base+jj+2*H_];
            float r  = sigax(gi[jj]       + enc_bi[jj]       + s0 + enc_bh[jj]);
            float z  = sigax(gi[jj+H_]    + enc_bi[jj+H_]    + s1 + enc_bh[jj+H_]);
            float n  = tanhax(gi[jj+2*H_] + enc_bi[jj+2*H_]  + r * (s2 + enc_bh[jj+2*H_]));
            float h  = g_h[i];
            float hn = (1.f - z) * n + z * h;
            g_h[i] = hn;
            g_enc_out[(b*L_ + t) * H_ + jj] = (t < lengths[b]) ? hn : 0.f;
        }
        gsync();
    }

    // ---- enc_keys (2048 tiles) + hidden0 gather (8 jobs) ----
    for (int j = slot; j < 2056; j += NSLOT) {
        if (j < 2048) {
            int mi = j >> 3, ni = j & 7;
            tileg<false>(g_enc_out, nullptr, H_, s2s_Wk, AS_, nullptr, g_enc_keys, AS_,
                         0, H_, mi*32, ni*64, t128, u, Asd[u], Bs[u]);
        } else {
            int jb = j - 2048;
            for (int e = t128; e < 8192; e += 128) {
                int i = jb * 8192 + e;
                int b = i >> 9, jj = i & 511;
                g_h[i] = g_enc_out[(b*L_ + lengths[b] - 1) * H_ + jj];
            }
        }
    }
    gsync();

    // ---- decoder: software-pipelined, 4 barriers/step ----
    for (int t = 0; t <= L_; t++) {
        const int tp = t - 1;
        // P1: q_t (K-split2: 64 jobs) ; dout_{t-1} (K-split2: 32 jobs)
        {
            int nq = (t < L_) ? 64 : 0, nd = (t > 0) ? 32 : 0;
            for (int j = slot; j < nq + nd; j += NSLOT) {
                if (j < nq) {
                    int tile = j >> 1, ks = j & 1;
                    int mi = tile >> 3, ni = tile & 7;
                    tileg<false>(g_h, nullptr, H_, s2s_Wq, AS_, nullptr,
                                 ks ? g_q2 : g_q, AS_,
                                 ks*256, ks*256+256, mi*32, ni*64, t128, u, Asd[u], Bs[u]);
                } else {
                    int j2 = j - nq; int tile = j2 >> 1, ks = j2 & 1;
                    int mi = tile >> 2, ni = tile & 3;
                    tileg<true>(g_h, nullptr, H_, W_out, H_, ks ? nullptr : b_out,
                                ks ? g_dout2 : g_dout, D_,
                                ks*256, ks*256+256, mi*32, ni*64, t128, u, Asd[u], Bs[u]);
                }
            }
            gsync();
        }
        // P2: pq_{t-1} (16 jobs, A = dout+dout2) ; s2s attention_t (128 jobs)
        {
            int np = (t > 0) ? 16 : 0, na = (t < L_) ? 128 : 0;
            for (int j = slot; j < np + na; j += NSLOT) {
                if (j < np) {
                    int mi = j >> 2, ni = j & 3;
                    tileg<false>(g_dout, g_dout2, D_, ptr_Wq, AP_, nullptr, g_pq, AP_,
                                 0, D_, mi*32, ni*64, t128, u, Asd[u], Bs[u]);
                } else {
                    attn_s2s_job(j - np, t, t128, u, scr[u], lengths, s2s_v);
                }
            }
            gsync();
        }
        // P3: gh_t + gic_t (K-split2: 384 jobs) ; ptr attention_{t-1} (128 jobs)
        {
            int ng = (t < L_) ? 384 : 0, nf = (t > 0) ? 128 : 0;
            for (int j = slot; j < ng + nf; j += NSLOT) {
                if (j < ng) {
                    if (j < 192) {
                        int tile = j >> 1, half = j & 1;
                        int mi = tile / 24, ni = tile - mi * 24;
                        tileg<true>(g_h, nullptr, H_, dec_Wh, H_, nullptr,
                                    half ? g_gh2 : g_gh, G3H_,
                                    half*256, half*256+256, mi*32, ni*64, t128, u, Asd[u], Bs[u]);
                    } else {
                        int j2 = j - 192; int tile = j2 >> 1, half = j2 & 1;
                        int mi = tile / 24, ni = tile - mi * 24;
                        tileg<true>(g_ctx, nullptr, H_, dec_Wi, H_ + D_, nullptr,
                                    half ? g_gic2 : g_gic, G3H_,
                                    half*256, half*256+256, mi*32, ni*64, t128, u, Asd[u], Bs[u]);
                    }
                } else {
                    ptr_attn_job(j - ng, tp, t128, u, scr[u], lengths, ptr_v,
                                 out_logits, out_preds);
                }
            }
            gsync();
        }
        // P4: GRU gate update -> h_{t+1}
        if (t < L_) {
            for (int i = gtid; i < B_ * H_; i += GSTRIDE) {
                int b = i >> 9, jj = i & 511;
                int ix = g_idx[t*B_ + b];
                const float* gx = g_decx_gi + (b*L_ + ix) * G3H_;
                int base = b * G3H_;
                float c0 = g_gic[base+jj]      + g_gic2[base+jj];
                float c1 = g_gic[base+jj+H_]   + g_gic2[base+jj+H_];
                float c2 = g_gic[base+jj+2*H_] + g_gic2[base+jj+2*H_];
                float h0 = g_gh[base+jj]       + g_gh2[base+jj];
                float h1 = g_gh[base+jj+H_]    + g_gh2[base+jj+H_];
                float h2 = g_gh[base+jj+2*H_]  + g_gh2[base+jj+2*H_];
                float r = sigax(gx[jj]      + c0 + dec_bi[jj]      + h0 + dec_bh[jj]);
                float z = sigax(gx[jj+H_]   + c1 + dec_bi[jj+H_]   + h1 + dec_bh[jj+H_]);
                float n = tanhax(gx[jj+2*H_] + c2 + dec_bi[jj+2*H_] +
                                 r * (h2 + dec_bh[jj+2*H_]));
                float h = g_h[i];
                g_h[i] = (1.f - z) * n + z * h;
            }
        }
        gsync();
    }
}

// ---------------- host ----------------
extern "C" void kernel_launch(void* const* d_in, const int* in_sizes, int n_in,
                              void* d_out, int out_size)
{
    const float* inputs  = (const float*)d_in[0];
    const int*   lengths = (const int*)  d_in[1];
    const int*   targets = (const int*)  d_in[2];
    const float* W_in    = (const float*)d_in[3];
    const float* b_in    = (const float*)d_in[4];
    const float* enc_Wi  = (const float*)d_in[5];
    const float* enc_Wh  = (const float*)d_in[6];
    const float* enc_bi  = (const float*)d_in[7];
    const float* enc_bh  = (const float*)d_in[8];
    const float* dec_Wi  = (const float*)d_in[9];
    const float* dec_Wh  = (const float*)d_in[10];
    const float* dec_bi  = (const float*)d_in[11];
    const float* dec_bh  = (const float*)d_in[12];
    const float* s2s_Wq  = (const float*)d_in[13];
    const float* s2s_Wk  = (const float*)d_in[14];
    const float* s2s_v   = (const float*)d_in[15];
    const float* W_out   = (const float*)d_in[16];
    const float* b_out   = (const float*)d_in[17];
    const float* ptr_Wq  = (const float*)d_in[18];
    const float* ptr_Wk  = (const float*)d_in[19];
    const float* ptr_v   = (const float*)d_in[20];

    float* out = (float*)d_out;
    float* out_logits = out;
    float* out_preds  = (out_size >= B_*L_*L_ + B_*L_) ? (out + B_*L_*L_) : nullptr;

    seq_kernel<<<NB, NT_>>>(inputs, lengths, targets, W_in, b_in,
                            enc_Wi, enc_Wh, enc_bi, enc_bh,
                            dec_Wi, dec_Wh, dec_bi, dec_bh,
                            s2s_Wq, s2s_Wk, s2s_v, W_out, b_out,
                            ptr_Wq, ptr_Wk, ptr_v,
                            out_logits, out_preds);
}